// round 2
// baseline (speedup 1.0000x reference)
#include <cuda_runtime.h>
#include <cuda_bf16.h>
#include <cstdint>

// Problem constants (fixed by setup_inputs)
#define Hh 40
#define Ww 40
#define NPIX 1600          // 40*40
#define HID 64
#define MODDIM 16

typedef unsigned long long u64;

// Scratch (allocation-free rule: __device__ globals)
__device__ float g_U[NPIX][HID];   // U[i][h] = x_i*W0 + y_i*W1 + s_i*Wsi + C[h]
__device__ float g_V[NPIX][HID];   // V[j][h] = -x_j*W0 - y_j*W1 + s_j*Wsj

// ---------------------------------------------------------------------------
// f32x2 packed helpers (Blackwell sm_100+). NOTE: only add/sub/mul/fma exist
// in packed form; relu is done with scalar FMNMX on the halves (alu pipe).
// ---------------------------------------------------------------------------
__device__ __forceinline__ u64 add2(u64 a, u64 b) {
    u64 r; asm("add.rn.f32x2 %0, %1, %2;" : "=l"(r) : "l"(a), "l"(b)); return r;
}
__device__ __forceinline__ u64 fma2(u64 a, u64 b, u64 c) {
    u64 r; asm("fma.rn.f32x2 %0, %1, %2, %3;" : "=l"(r) : "l"(a), "l"(b), "l"(c)); return r;
}
__device__ __forceinline__ float2 unpack2(u64 v) {
    float2 r; asm("mov.b64 {%0, %1}, %2;" : "=f"(r.x), "=f"(r.y) : "l"(v)); return r;
}
__device__ __forceinline__ u64 pack2(float lo, float hi) {
    u64 r; asm("mov.b64 %0, {%1, %2};" : "=l"(r) : "f"(lo), "f"(hi)); return r;
}
// relu on both halves of a packed f32x2 (2x FMNMX, alu pipe — free wrt fma pipe)
__device__ __forceinline__ u64 relu2(u64 v) {
    float2 t = unpack2(v);
    return pack2(fmaxf(t.x, 0.0f), fmaxf(t.y, 0.0f));
}

// ---------------------------------------------------------------------------
// Kernel 1: prep — resize+mean structure map, build C, write U and V
// ---------------------------------------------------------------------------
__global__ void prep_kernel(const int* __restrict__ qmod_p,
                            const int* __restrict__ kmod_p,
                            const float* __restrict__ smap,      // (4,1,80,80)
                            const float* __restrict__ mod_embed, // (3,16)
                            const float* __restrict__ W1,        // (36,64)
                            const float* __restrict__ b1)        // (64,)
{
    __shared__ float mv[2 * MODDIM];
    __shared__ float Cs[HID];

    const int tid = threadIdx.x;

    if (tid < 2 * MODDIM) {
        int m = (tid < MODDIM) ? *qmod_p : *kmod_p;
        mv[tid] = mod_embed[m * MODDIM + (tid & (MODDIM - 1))];
    }
    __syncthreads();

    if (tid < HID) {
        float c = b1[tid];
        #pragma unroll
        for (int k = 0; k < 2 * MODDIM; k++)
            c += mv[k] * W1[(2 + k) * HID + tid];
        Cs[tid] = c;
    }
    __syncthreads();

    const int n = blockIdx.x * blockDim.x + tid;
    if (n >= NPIX) return;

    const int r = n / Ww;
    const int c = n % Ww;

    // antialiased linear resize 80->40: taps at 2o-1..2o+2, raw w {.25,.75,.75,.25},
    // renormalized by sum of in-bounds weights (matches jax edge handling)
    const float raw[4] = {0.25f, 0.75f, 0.75f, 0.25f};
    float wy[4], wx[4];
    float sy = 0.f, sx = 0.f;
    #pragma unroll
    for (int t = 0; t < 4; t++) {
        int iy = 2 * r - 1 + t;
        wy[t] = (iy >= 0 && iy < 80) ? raw[t] : 0.f;
        sy += wy[t];
        int ix = 2 * c - 1 + t;
        wx[t] = (ix >= 0 && ix < 80) ? raw[t] : 0.f;
        sx += wx[t];
    }
    float acc = 0.f;
    #pragma unroll
    for (int b = 0; b < 4; b++) {
        const float* base = smap + b * 6400;
        #pragma unroll
        for (int ty = 0; ty < 4; ty++) {
            if (wy[ty] == 0.f) continue;
            int iy = 2 * r - 1 + ty;
            float rowacc = 0.f;
            #pragma unroll
            for (int tx = 0; tx < 4; tx++) {
                if (wx[tx] == 0.f) continue;
                int ix = 2 * c - 1 + tx;
                rowacc += wx[tx] * base[iy * 80 + ix];
            }
            acc += wy[ty] * rowacc;
        }
    }
    const float s = acc / (sy * sx) * 0.25f;   // mean over 4 batches

    const float x = (float)c * (1.0f / 39.0f) - 0.5f;
    const float y = (float)r * (1.0f / 39.0f) - 0.5f;

    #pragma unroll 8
    for (int h = 0; h < HID; h++) {
        float w0  = W1[h];
        float w1  = W1[HID + h];
        float wsi = W1[34 * HID + h];
        float wsj = W1[35 * HID + h];
        g_U[n][h] =  x * w0 + y * w1 + s * wsi + Cs[h];
        g_V[n][h] = -x * w0 - y * w1 + s * wsj;
    }
}

// ---------------------------------------------------------------------------
// Kernel 2: main — 64x64 output tile per block, 4x4 per thread, f32x2 packed
// ---------------------------------------------------------------------------
#define TILE 64
#define SSTRIDE 68   // pad to 68 floats: keeps float2/float4 alignment, kills bank conflicts

__global__ void __launch_bounds__(256) rpe_main_kernel(
    float* __restrict__ out,
    const float* __restrict__ W2,    // (64,1)
    const float* __restrict__ b2)    // (1,)
{
    __shared__ float Us[TILE * SSTRIDE];
    __shared__ float Vs[TILE * SSTRIDE];
    __shared__ u64   w2s[HID / 2];

    const int tid = threadIdx.x;
    const int i0 = blockIdx.y * TILE;
    const int j0 = blockIdx.x * TILE;

    // stage U and V tiles (each 64 rows x 64 floats) via float4
    #pragma unroll
    for (int k = tid; k < TILE * (HID / 4); k += 256) {
        int row  = k >> 4;
        int col4 = (k & 15) << 2;
        *(float4*)&Us[row * SSTRIDE + col4] = *(const float4*)&g_U[i0 + row][col4];
        *(float4*)&Vs[row * SSTRIDE + col4] = *(const float4*)&g_V[j0 + row][col4];
    }
    if (tid < HID / 2)
        w2s[tid] = *(const u64*)&W2[2 * tid];
    __syncthreads();

    const int tx = tid & 15;          // j direction
    const int ty = tid >> 4;          // i direction
    const int ii = ty * 4;
    const int jj = tx * 4;

    u64 acc[4][4];
    #pragma unroll
    for (int a = 0; a < 4; a++)
        #pragma unroll
        for (int b = 0; b < 4; b++)
            acc[a][b] = 0ull;

    #pragma unroll
    for (int t = 0; t < HID / 2; t++) {
        const int h = t * 2;
        u64 u[4], v[4];
        #pragma unroll
        for (int a = 0; a < 4; a++)
            u[a] = *(const u64*)&Us[(ii + a) * SSTRIDE + h];
        #pragma unroll
        for (int b = 0; b < 4; b++)
            v[b] = *(const u64*)&Vs[(jj + b) * SSTRIDE + h];
        const u64 w2p = w2s[t];
        #pragma unroll
        for (int a = 0; a < 4; a++) {
            #pragma unroll
            for (int b = 0; b < 4; b++) {
                u64 sres = relu2(add2(u[a], v[b]));
                acc[a][b] = fma2(sres, w2p, acc[a][b]);
            }
        }
    }

    const float b2v = *b2;
    #pragma unroll
    for (int a = 0; a < 4; a++) {
        const int gi = i0 + ii + a;
        #pragma unroll
        for (int b = 0; b < 4; b++) {
            float2 p = unpack2(acc[a][b]);
            out[gi * NPIX + (j0 + jj + b)] = p.x + p.y + b2v;
        }
    }
}

// ---------------------------------------------------------------------------
// Launch
// ---------------------------------------------------------------------------
extern "C" void kernel_launch(void* const* d_in, const int* in_sizes, int n_in,
                              void* d_out, int out_size) {
    // inputs: 0:h 1:w 2:q_mod 3:k_mod 4:structure_map 5:mod_embed 6:W1 7:b1 8:W2 9:b2
    const int*   qmod = (const int*)d_in[2];
    const int*   kmod = (const int*)d_in[3];
    const float* smap = (const float*)d_in[4];
    const float* memb = (const float*)d_in[5];
    const float* W1   = (const float*)d_in[6];
    const float* b1   = (const float*)d_in[7];
    const float* W2   = (const float*)d_in[8];
    const float* b2   = (const float*)d_in[9];
    float* out = (float*)d_out;

    prep_kernel<<<(NPIX + 255) / 256, 256>>>(qmod, kmod, smap, memb, W1, b1);

    dim3 grid(NPIX / TILE, NPIX / TILE);   // 25 x 25
    rpe_main_kernel<<<grid, 256>>>(out, W2, b2);
}

// round 3
// speedup vs baseline: 1.9200x; 1.9200x over previous
#include <cuda_runtime.h>
#include <cstdint>

#define NPIX  1600
#define WIDTH 40
#define HID   64
#define MODDIM 16
#define TILE  64
#define UST   64     // UsT row stride (floats) — conflict-free for i-quad LDS.128
#define VST   132    // Vsd row stride (floats) — keeps 16B alignment, spreads jg banks
#define OST   68     // out staging stride (floats) — 16B aligned
#define SMEM_FLOATS (TILE*UST + TILE*VST + 128)   // 4096 + 8448 + 128 = 12672
#define SMEM_BYTES  (SMEM_FLOATS * 4)             // 50688

typedef unsigned long long u64;

// persistent scratch (allocation-free rule)
__device__ float g_UT[HID][NPIX];   // U transposed: UT[h][i]
__device__ float g_V [NPIX][HID];   // V[j][h]

// ---- packed f32x2 helpers (add/fma exist packed; relu via FMNMX on halves) ----
static __device__ __forceinline__ u64 add2(u64 a, u64 b) {
    u64 r; asm("add.rn.f32x2 %0, %1, %2;" : "=l"(r) : "l"(a), "l"(b)); return r;
}
static __device__ __forceinline__ u64 fma2(u64 a, u64 b, u64 c) {
    u64 r; asm("fma.rn.f32x2 %0, %1, %2, %3;" : "=l"(r) : "l"(a), "l"(b), "l"(c)); return r;
}
static __device__ __forceinline__ float2 up2(u64 v) {
    float2 r; asm("mov.b64 {%0, %1}, %2;" : "=f"(r.x), "=f"(r.y) : "l"(v)); return r;
}
static __device__ __forceinline__ u64 pk2(float a, float b) {
    u64 r; asm("mov.b64 %0, {%1, %2};" : "=l"(r) : "f"(a), "f"(b)); return r;
}
static __device__ __forceinline__ u64 relu2(u64 v) {
    float2 t = up2(v);
    return pk2(fmaxf(t.x, 0.0f), fmaxf(t.y, 0.0f));
}

// ---------------------------------------------------------------------------
// prep: 25 blocks x 256 threads. Computes s_mean (antialiased resize 80->40,
// batch mean), modality constant C[h], then writes g_UT (coalesced over n)
// and g_V (coalesced over h).
// ---------------------------------------------------------------------------
__global__ void __launch_bounds__(256) prep_kernel(
    const int* __restrict__ qmod_p, const int* __restrict__ kmod_p,
    const float* __restrict__ smap,      // (4,1,80,80)
    const float* __restrict__ memb,      // (3,16)
    const float* __restrict__ W1,        // (36,64)
    const float* __restrict__ b1)        // (64,)
{
    __shared__ float part[64][5];
    __shared__ float s_sh[64];
    __shared__ float mv[2 * MODDIM];
    __shared__ float Cs[HID];

    const int tid = threadIdx.x;
    const int n0  = blockIdx.x * 64;
    const float raw[4] = {0.25f, 0.75f, 0.75f, 0.25f};

    if (tid < 2 * MODDIM) {
        int m = (tid < MODDIM) ? *qmod_p : *kmod_p;
        mv[tid] = memb[m * MODDIM + (tid & (MODDIM - 1))];
    }

    // s partial: one (pixel, batch) per thread, 16 taps
    {
        const int pix = tid >> 2, b = tid & 3;
        const int n = n0 + pix;
        const int r = n / WIDTH, c = n % WIDTH;
        const float* base = smap + b * 6400;
        float acc = 0.f;
        #pragma unroll
        for (int ty = 0; ty < 4; ty++) {
            int iy = 2 * r - 1 + ty;
            if (iy < 0 || iy >= 80) continue;
            #pragma unroll
            for (int tx = 0; tx < 4; tx++) {
                int ix = 2 * c - 1 + tx;
                if (ix < 0 || ix >= 80) continue;
                acc += raw[ty] * raw[tx] * base[iy * 80 + ix];
            }
        }
        part[pix][b] = acc;
    }
    __syncthreads();

    if (tid < HID) {                      // C[h]
        float cc = b1[tid];
        #pragma unroll
        for (int k = 0; k < 2 * MODDIM; k++)
            cc += mv[k] * W1[(2 + k) * HID + tid];
        Cs[tid] = cc;
    } else if (tid < 128) {               // finalize s (edge renorm, batch mean)
        const int p = tid - 64;
        const int n = n0 + p;
        const int r = n / WIDTH, c = n % WIDTH;
        float sy = 0.f, sx = 0.f;
        #pragma unroll
        for (int t = 0; t < 4; t++) {
            int iy = 2 * r - 1 + t; if (iy >= 0 && iy < 80) sy += raw[t];
            int ix = 2 * c - 1 + t; if (ix >= 0 && ix < 80) sx += raw[t];
        }
        s_sh[p] = (part[p][0] + part[p][1] + part[p][2] + part[p][3])
                  / (sy * sx) * 0.25f;
    }
    __syncthreads();

    // phase U: thread = (nn = tid&63 spans n  -> coalesced stores, hg = tid>>6)
    {
        const int nn = tid & 63, hg = tid >> 6;
        const int n = n0 + nn;
        const int r = n / WIDTH, c = n % WIDTH;
        const float x = (float)c * (1.0f / 39.0f) - 0.5f;
        const float y = (float)r * (1.0f / 39.0f) - 0.5f;
        const float s = s_sh[nn];
        #pragma unroll
        for (int k = 0; k < 16; k++) {
            int h = hg * 16 + k;
            g_UT[h][n] = x * W1[h] + y * W1[HID + h] + s * W1[34 * HID + h] + Cs[h];
        }
    }
    // phase V: thread = (hh = tid&63 spans h -> coalesced stores, ng = tid>>6)
    {
        const int hh = tid & 63, ng = tid >> 6;
        const float w0  = W1[hh];
        const float w1  = W1[HID + hh];
        const float wsj = W1[35 * HID + hh];
        #pragma unroll
        for (int k = 0; k < 16; k++) {
            int nn = ng * 16 + k;
            int n = n0 + nn;
            int r = n / WIDTH, c = n % WIDTH;
            float x = (float)c * (1.0f / 39.0f) - 0.5f;
            float y = (float)r * (1.0f / 39.0f) - 0.5f;
            g_V[n][hh] = -x * w0 - y * w1 + s_sh[nn] * wsj;
        }
    }
}

// ---------------------------------------------------------------------------
// main: 64x64 tile / block, 4i x 4j per thread, f32x2 packed over the i-pair.
// UsT: [h][i] (LDS.128 i-quads, conflict-free).  Vsd: [j][2h] value-duplicated
// (LDS.64 broadcast).  w2d: [2h] duplicated.  No pack MOVs needed anywhere.
// ---------------------------------------------------------------------------
__global__ void __launch_bounds__(256) rpe_main_kernel(
    float* __restrict__ out,
    const float* __restrict__ W2,    // (64,1)
    const float* __restrict__ b2)    // (1,)
{
    extern __shared__ float sm[];
    float* UsT = sm;                    // TILE*UST
    float* Vsd = sm + TILE * UST;       // TILE*VST
    float* w2d = Vsd + TILE * VST;      // 128

    const int tid = threadIdx.x;
    const int i0 = blockIdx.y * TILE;
    const int j0 = blockIdx.x * TILE;

    // stage UsT (coalesced LDG.128 per h-row)
    #pragma unroll
    for (int k = tid; k < TILE * 16; k += 256) {
        int h = k >> 4, c4 = k & 15;
        *(float4*)&UsT[h * UST + c4 * 4] = *(const float4*)&g_UT[h][i0 + c4 * 4];
    }
    // stage Vsd with h-duplication
    #pragma unroll
    for (int k = tid; k < TILE * 16; k += 256) {
        int j = k >> 4, c4 = k & 15;
        float4 t = *(const float4*)&g_V[j0 + j][c4 * 4];
        float* d = &Vsd[j * VST + c4 * 8];
        ((float4*)d)[0] = make_float4(t.x, t.x, t.y, t.y);
        ((float4*)d)[1] = make_float4(t.z, t.z, t.w, t.w);
    }
    if (tid < HID) { float w = W2[tid]; w2d[2 * tid] = w; w2d[2 * tid + 1] = w; }
    __syncthreads();

    const int ig = tid & 15, jg = tid >> 4;
    const int ii = ig * 4, jj = jg * 4;

    u64 acc[2][4];
    #pragma unroll
    for (int a = 0; a < 2; a++)
        #pragma unroll
        for (int b = 0; b < 4; b++) acc[a][b] = 0ull;

    #pragma unroll 8
    for (int h = 0; h < HID; h++) {
        ulonglong2 u = *(const ulonglong2*)&UsT[h * UST + ii];   // LDS.128: (i,i+1),(i+2,i+3)
        u64 ww = *(const u64*)&w2d[2 * h];                        // (w_h, w_h)
        #pragma unroll
        for (int b = 0; b < 4; b++) {
            u64 vv = *(const u64*)&Vsd[(jj + b) * VST + 2 * h];   // (v, v) broadcast
            acc[0][b] = fma2(relu2(add2(u.x, vv)), ww, acc[0][b]);
            acc[1][b] = fma2(relu2(add2(u.y, vv)), ww, acc[1][b]);
        }
    }
    __syncthreads();

    // epilogue through smem staging for coalesced global stores
    const float b2v = *b2;
    float* outS = sm;   // 64*OST = 4352 floats, fits
    #pragma unroll
    for (int a = 0; a < 2; a++)
        #pragma unroll
        for (int b = 0; b < 4; b++) {
            float2 p = up2(acc[a][b]);
            outS[(ii + 2 * a)     * OST + jj + b] = p.x + b2v;
            outS[(ii + 2 * a + 1) * OST + jj + b] = p.y + b2v;
        }
    __syncthreads();
    #pragma unroll
    for (int k = tid; k < TILE * 16; k += 256) {
        int r = k >> 4, c4 = k & 15;
        float4 t = *(const float4*)&outS[r * OST + c4 * 4];
        *(float4*)&out[(u64)(i0 + r) * NPIX + j0 + c4 * 4] = t;
    }
}

// ---------------------------------------------------------------------------
extern "C" void kernel_launch(void* const* d_in, const int* in_sizes, int n_in,
                              void* d_out, int out_size) {
    // 0:h 1:w 2:q_mod 3:k_mod 4:structure_map 5:mod_embed 6:W1 7:b1 8:W2 9:b2
    const int*   qmod = (const int*)d_in[2];
    const int*   kmod = (const int*)d_in[3];
    const float* smap = (const float*)d_in[4];
    const float* memb = (const float*)d_in[5];
    const float* W1   = (const float*)d_in[6];
    const float* b1   = (const float*)d_in[7];
    const float* W2   = (const float*)d_in[8];
    const float* b2   = (const float*)d_in[9];
    float* out = (float*)d_out;

    static bool attr_done = false;
    if (!attr_done) {
        cudaFuncSetAttribute(rpe_main_kernel,
                             cudaFuncAttributeMaxDynamicSharedMemorySize, SMEM_BYTES);
        attr_done = true;
    }

    prep_kernel<<<NPIX / 64, 256>>>(qmod, kmod, smap, memb, W1, b1);
    dim3 grid(NPIX / TILE, NPIX / TILE);   // 25 x 25
    rpe_main_kernel<<<grid, 256, SMEM_BYTES>>>(out, W2, b2);
}

// round 4
// speedup vs baseline: 2.1860x; 1.1386x over previous
#include <cuda_runtime.h>
#include <cstdint>

#define NPIX  1600
#define WIDTH 40
#define HID   64
#define MODDIM 16
#define TI 64          // i-tile
#define TJ 32          // j-tile
#define ST 68          // smem row stride (floats): lane-consecutive rows -> bank stride 4
#define OT 36          // out staging stride

typedef unsigned long long u64;

// persistent scratch (allocation-free rule) — both natural [n][h] layout
__device__ float g_U[NPIX][HID];
__device__ float g_V[NPIX][HID];

// ---- packed f32x2 helpers ----
static __device__ __forceinline__ u64 add2(u64 a, u64 b) {
    u64 r; asm("add.rn.f32x2 %0, %1, %2;" : "=l"(r) : "l"(a), "l"(b)); return r;
}
static __device__ __forceinline__ u64 fma2(u64 a, u64 b, u64 c) {
    u64 r; asm("fma.rn.f32x2 %0, %1, %2, %3;" : "=l"(r) : "l"(a), "l"(b), "l"(c)); return r;
}
static __device__ __forceinline__ float2 up2(u64 v) {
    float2 r; asm("mov.b64 {%0, %1}, %2;" : "=f"(r.x), "=f"(r.y) : "l"(v)); return r;
}
static __device__ __forceinline__ u64 pk2(float a, float b) {
    u64 r; asm("mov.b64 %0, {%1, %2};" : "=l"(r) : "f"(a), "f"(b)); return r;
}
static __device__ __forceinline__ u64 relu2(u64 v) {
    float2 t = up2(v);
    return pk2(fmaxf(t.x, 0.0f), fmaxf(t.y, 0.0f));
}

// ---------------------------------------------------------------------------
// prep: 25 blocks x 256 threads. s_mean (antialiased resize 80->40 + batch
// mean), C[h], then U and V written h-coalesced into natural [n][h] layout.
// ---------------------------------------------------------------------------
__global__ void __launch_bounds__(256) prep_kernel(
    const int* __restrict__ qmod_p, const int* __restrict__ kmod_p,
    const float* __restrict__ smap,      // (4,1,80,80)
    const float* __restrict__ memb,      // (3,16)
    const float* __restrict__ W1,        // (36,64)
    const float* __restrict__ b1)        // (64,)
{
    __shared__ float part[64][5];
    __shared__ float s_sh[64];
    __shared__ float mv[2 * MODDIM];
    __shared__ float Cs[HID];

    const int tid = threadIdx.x;
    const int n0  = blockIdx.x * 64;
    const float raw[4] = {0.25f, 0.75f, 0.75f, 0.25f};

    if (tid < 2 * MODDIM) {
        int m = (tid < MODDIM) ? *qmod_p : *kmod_p;
        mv[tid] = memb[m * MODDIM + (tid & (MODDIM - 1))];
    }

    // s partial: one (pixel, batch) per thread, 16 taps
    {
        const int pix = tid >> 2, b = tid & 3;
        const int n = n0 + pix;
        const int r = n / WIDTH, c = n % WIDTH;
        const float* base = smap + b * 6400;
        float acc = 0.f;
        #pragma unroll
        for (int ty = 0; ty < 4; ty++) {
            int iy = 2 * r - 1 + ty;
            if (iy < 0 || iy >= 80) continue;
            #pragma unroll
            for (int tx = 0; tx < 4; tx++) {
                int ix = 2 * c - 1 + tx;
                if (ix < 0 || ix >= 80) continue;
                acc += raw[ty] * raw[tx] * base[iy * 80 + ix];
            }
        }
        part[pix][b] = acc;
    }
    __syncthreads();

    if (tid < HID) {                      // C[h]
        float cc = b1[tid];
        #pragma unroll
        for (int k = 0; k < 2 * MODDIM; k++)
            cc += mv[k] * W1[(2 + k) * HID + tid];
        Cs[tid] = cc;
    } else if (tid < 128) {               // finalize s (edge renorm, batch mean)
        const int p = tid - 64;
        const int n = n0 + p;
        const int r = n / WIDTH, c = n % WIDTH;
        float sy = 0.f, sx = 0.f;
        #pragma unroll
        for (int t = 0; t < 4; t++) {
            int iy = 2 * r - 1 + t; if (iy >= 0 && iy < 80) sy += raw[t];
            int ix = 2 * c - 1 + t; if (ix >= 0 && ix < 80) sx += raw[t];
        }
        s_sh[p] = (part[p][0] + part[p][1] + part[p][2] + part[p][3])
                  / (sy * sx) * 0.25f;
    }
    __syncthreads();

    // U and V: thread hh = tid&63 spans h (coalesced 256B stores), 16 n's each
    {
        const int hh = tid & 63, ng = tid >> 6;
        const float w0  = W1[hh];
        const float w1  = W1[HID + hh];
        const float wsi = W1[34 * HID + hh];
        const float wsj = W1[35 * HID + hh];
        const float ch  = Cs[hh];
        #pragma unroll
        for (int k = 0; k < 16; k++) {
            int nn = ng * 16 + k;
            int n = n0 + nn;
            int r = n / WIDTH, c = n % WIDTH;
            float x = (float)c * (1.0f / 39.0f) - 0.5f;
            float y = (float)r * (1.0f / 39.0f) - 0.5f;
            float s = s_sh[nn];
            float xy = x * w0 + y * w1;
            g_U[n][hh] =  xy + s * wsi + ch;
            g_V[n][hh] = -xy + s * wsj;
        }
    }
}

// ---------------------------------------------------------------------------
// main: 64x32 tile / block (128 threads), 4i x 4j per thread, packed over h.
// i = ig + 16a (lane-consecutive rows -> conflict-free LDS.128 with ST=68),
// j = jg + 8b (2 addrs per warp -> broadcast). All layouts natural, no dup.
// ---------------------------------------------------------------------------
__global__ void __launch_bounds__(128) rpe_main_kernel(
    float* __restrict__ out,
    const float* __restrict__ W2,    // (64,)
    const float* __restrict__ b2)    // (1,)
{
    __shared__ float Us[TI * ST];    // 64*68*4 = 17408 B
    __shared__ float Vs[TJ * ST];    // 32*68*4 =  8704 B
    __shared__ float w2s[HID];

    const int tid = threadIdx.x;
    const int i0 = blockIdx.y * TI;
    const int j0 = blockIdx.x * TJ;

    // stage (coalesced LDG.128; STS banks spread: 4*c4 over 8 banks/phase)
    #pragma unroll
    for (int k = tid; k < TI * 16; k += 128) {
        int r = k >> 4, c4 = (k & 15) << 2;
        *(float4*)&Us[r * ST + c4] = *(const float4*)&g_U[i0 + r][c4];
    }
    #pragma unroll
    for (int k = tid; k < TJ * 16; k += 128) {
        int r = k >> 4, c4 = (k & 15) << 2;
        *(float4*)&Vs[r * ST + c4] = *(const float4*)&g_V[j0 + r][c4];
    }
    if (tid < 16)
        *(float4*)&w2s[tid * 4] = *(const float4*)&W2[tid * 4];
    __syncthreads();

    const int ig = tid & 15;    // i = ig + 16a
    const int jg = tid >> 4;    // j = jg + 8b

    u64 acc[4][4];
    #pragma unroll
    for (int a = 0; a < 4; a++)
        #pragma unroll
        for (int b = 0; b < 4; b++) acc[a][b] = 0ull;

    #pragma unroll 2
    for (int h = 0; h < HID; h += 4) {
        ulonglong2 w = *(const ulonglong2*)&w2s[h];
        ulonglong2 u[4], v[4];
        #pragma unroll
        for (int a = 0; a < 4; a++)
            u[a] = *(const ulonglong2*)&Us[(ig + 16 * a) * ST + h];
        #pragma unroll
        for (int b = 0; b < 4; b++)
            v[b] = *(const ulonglong2*)&Vs[(jg + 8 * b) * ST + h];
        #pragma unroll
        for (int a = 0; a < 4; a++)
            #pragma unroll
            for (int b = 0; b < 4; b++) {
                acc[a][b] = fma2(relu2(add2(u[a].x, v[b].x)), w.x, acc[a][b]);
                acc[a][b] = fma2(relu2(add2(u[a].y, v[b].y)), w.y, acc[a][b]);
            }
    }
    __syncthreads();   // everyone done reading Us before reuse as staging

    // epilogue: horizontal add, stage, coalesced float4 stores
    const float b2v = *b2;
    float* outS = Us;   // reuse (64*36 = 2304 <= 64*68)
    #pragma unroll
    for (int a = 0; a < 4; a++)
        #pragma unroll
        for (int b = 0; b < 4; b++) {
            float2 p = up2(acc[a][b]);
            outS[(ig + 16 * a) * OT + (jg + 8 * b)] = p.x + p.y + b2v;
        }
    __syncthreads();
    #pragma unroll
    for (int k = tid; k < TI * 8; k += 128) {
        int r = k >> 3, c4 = (k & 7) << 2;
        *(float4*)&out[(u64)(i0 + r) * NPIX + j0 + c4] = *(const float4*)&outS[r * OT + c4];
    }
}

// ---------------------------------------------------------------------------
extern "C" void kernel_launch(void* const* d_in, const int* in_sizes, int n_in,
                              void* d_out, int out_size) {
    // 0:h 1:w 2:q_mod 3:k_mod 4:structure_map 5:mod_embed 6:W1 7:b1 8:W2 9:b2
    const int*   qmod = (const int*)d_in[2];
    const int*   kmod = (const int*)d_in[3];
    const float* smap = (const float*)d_in[4];
    const float* memb = (const float*)d_in[5];
    const float* W1   = (const float*)d_in[6];
    const float* b1   = (const float*)d_in[7];
    const float* W2   = (const float*)d_in[8];
    const float* b2   = (const float*)d_in[9];
    float* out = (float*)d_out;

    prep_kernel<<<NPIX / 64, 256>>>(qmod, kmod, smap, memb, W1, b1);

    dim3 grid(NPIX / TJ, NPIX / TI);   // 50 x 25 = 1250 blocks
    rpe_main_kernel<<<grid, 128>>>(out, W2, b2);
}